// round 1
// baseline (speedup 1.0000x reference)
#include <cuda_runtime.h>
#include <math.h>

#define BB 4
#define NN 2048
#define MM 2048
#define DD 1024
#define HH 16
#define DKK 64
#define RR (BB*NN)          // 8192 rows for projections
#define NEGV -1e32f

// -------- scratch (static device allocations are the sanctioned workaround) ----
__device__ float g_Q[(size_t)BB*HH*NN*DKK];      // (b,h,n,dk)  33.5 MB
__device__ float g_K[(size_t)BB*HH*MM*DKK];      // (b,h,m,dk)
__device__ float g_V[(size_t)BB*HH*MM*DKK];      // (b,h,m,dk)
__device__ float g_Wt[(size_t)BB*NN*HH*DKK];     // (b,n,h,dk)
__device__ float g_beta_scratch[(size_t)BB*HH*NN*MM]; // fallback if out lacks beta

// ============================================================================
// SGEMM: C[r,c] = sum_k A[r,k]*W[c,k] + bias[c]    (torch Linear: x @ W.T + b)
// 128x128 tile, BK=8, 256 threads, 8x8 per thread.
// SPLIT=1: write into (b,h,seq,dk) layout. SPLIT=0: plain row-major.
// ============================================================================
template<int SPLIT>
__global__ void __launch_bounds__(256) proj_kernel(const float* __restrict__ A,
                                                   const float* __restrict__ W,
                                                   const float* __restrict__ bias,
                                                   float* __restrict__ out)
{
    __shared__ float As[8][128];
    __shared__ float Ws[8][128];
    const int tid  = threadIdx.x;
    const int row0 = blockIdx.y * 128;
    const int col0 = blockIdx.x * 128;
    const int trow = (tid >> 4) << 3;
    const int tcol = (tid & 15) << 3;
    const int lrow = tid >> 1;
    const int lk   = (tid & 1) << 2;

    const float* Ap = A + (size_t)(row0 + lrow) * DD + lk;
    const float* Wp = W + (size_t)(col0 + lrow) * DD + lk;

    float acc[8][8];
    #pragma unroll
    for (int i = 0; i < 8; i++)
        #pragma unroll
        for (int j = 0; j < 8; j++) acc[i][j] = 0.f;

    for (int k0 = 0; k0 < DD; k0 += 8) {
        float4 av = *(const float4*)(Ap + k0);
        float4 wv = *(const float4*)(Wp + k0);
        __syncthreads();
        As[lk+0][lrow] = av.x; As[lk+1][lrow] = av.y;
        As[lk+2][lrow] = av.z; As[lk+3][lrow] = av.w;
        Ws[lk+0][lrow] = wv.x; Ws[lk+1][lrow] = wv.y;
        Ws[lk+2][lrow] = wv.z; Ws[lk+3][lrow] = wv.w;
        __syncthreads();
        #pragma unroll
        for (int k = 0; k < 8; k++) {
            float4 a0 = *(const float4*)&As[k][trow];
            float4 a1 = *(const float4*)&As[k][trow+4];
            float4 b0 = *(const float4*)&Ws[k][tcol];
            float4 b1 = *(const float4*)&Ws[k][tcol+4];
            float a[8] = {a0.x,a0.y,a0.z,a0.w,a1.x,a1.y,a1.z,a1.w};
            float b[8] = {b0.x,b0.y,b0.z,b0.w,b1.x,b1.y,b1.z,b1.w};
            #pragma unroll
            for (int i = 0; i < 8; i++)
                #pragma unroll
                for (int j = 0; j < 8; j++)
                    acc[i][j] = fmaf(a[i], b[j], acc[i][j]);
        }
    }

    #pragma unroll
    for (int i = 0; i < 8; i++) {
        const int r  = row0 + trow + i;
        const int bb = r >> 11;        // / 2048
        const int nn = r & 2047;
        #pragma unroll
        for (int j = 0; j < 8; j++) {
            const int c = col0 + tcol + j;
            const float val = acc[i][j] + bias[c];
            if (SPLIT) {
                const int hh = c >> 6;
                const int dk = c & 63;
                out[((((size_t)bb*HH + hh)*NN + nn) << 6) + dk] = val;
            } else {
                out[(size_t)r * DD + c] = val;
            }
        }
    }
}

// ============================================================================
// Scores: per (b,h): S = Q (N x 64) @ K^T (64 x M) * scale, masked -> beta (raw)
// 128x128 output tile, full K=64 in smem (transposed, stride 132). Dynamic smem.
// ============================================================================
__global__ void __launch_bounds__(256) scores_kernel(const int* __restrict__ mask,
                                                     float* __restrict__ beta)
{
    extern __shared__ float sm[];
    float (*Qs)[132] = (float(*)[132])sm;              // [64][132]
    float (*Ks)[132] = (float(*)[132])(sm + 64*132);

    const int tid = threadIdx.x;
    const int z   = blockIdx.z;        // b*H + h
    const int b   = z >> 4;
    const int m0  = blockIdx.x * 128;
    const int n0  = blockIdx.y * 128;

    const float* Qbase = g_Q + (size_t)z * NN * DKK;
    const float* Kbase = g_K + (size_t)z * MM * DKK;

    const int lr = tid >> 4;           // 0..15
    const int lc = (tid & 15) << 2;    // 0..60 step 4
    #pragma unroll
    for (int it = 0; it < 8; it++) {
        const int row = lr + it*16;
        float4 qv = *(const float4*)(Qbase + (size_t)(n0 + row)*DKK + lc);
        float4 kv = *(const float4*)(Kbase + (size_t)(m0 + row)*DKK + lc);
        Qs[lc+0][row] = qv.x; Qs[lc+1][row] = qv.y;
        Qs[lc+2][row] = qv.z; Qs[lc+3][row] = qv.w;
        Ks[lc+0][row] = kv.x; Ks[lc+1][row] = kv.y;
        Ks[lc+2][row] = kv.z; Ks[lc+3][row] = kv.w;
    }
    __syncthreads();

    const int trow = (tid >> 4) << 3;
    const int tcol = (tid & 15) << 3;
    float acc[8][8];
    #pragma unroll
    for (int i = 0; i < 8; i++)
        #pragma unroll
        for (int j = 0; j < 8; j++) acc[i][j] = 0.f;

    #pragma unroll 8
    for (int k = 0; k < 64; k++) {
        float4 a0 = *(const float4*)&Qs[k][trow];
        float4 a1 = *(const float4*)&Qs[k][trow+4];
        float4 b0 = *(const float4*)&Ks[k][tcol];
        float4 b1 = *(const float4*)&Ks[k][tcol+4];
        float a[8] = {a0.x,a0.y,a0.z,a0.w,a1.x,a1.y,a1.z,a1.w};
        float bb[8] = {b0.x,b0.y,b0.z,b0.w,b1.x,b1.y,b1.z,b1.w};
        #pragma unroll
        for (int i = 0; i < 8; i++)
            #pragma unroll
            for (int j = 0; j < 8; j++)
                acc[i][j] = fmaf(a[i], bb[j], acc[i][j]);
    }

    const float scl = 0.125f;   // 1/sqrt(64)
    #pragma unroll
    for (int i = 0; i < 8; i++) {
        const int n = n0 + trow + i;
        const int* mrow = mask + ((size_t)b*NN + n)*MM + m0 + tcol;
        float* brow = beta + ((size_t)z*NN + n)*MM + m0 + tcol;
        int4 mk0 = *(const int4*)(mrow);
        int4 mk1 = *(const int4*)(mrow + 4);
        float4 o0, o1;
        o0.x = (mk0.x == 1) ? NEGV : acc[i][0]*scl;
        o0.y = (mk0.y == 1) ? NEGV : acc[i][1]*scl;
        o0.z = (mk0.z == 1) ? NEGV : acc[i][2]*scl;
        o0.w = (mk0.w == 1) ? NEGV : acc[i][3]*scl;
        o1.x = (mk1.x == 1) ? NEGV : acc[i][4]*scl;
        o1.y = (mk1.y == 1) ? NEGV : acc[i][5]*scl;
        o1.z = (mk1.z == 1) ? NEGV : acc[i][6]*scl;
        o1.w = (mk1.w == 1) ? NEGV : acc[i][7]*scl;
        *(float4*)brow       = o0;
        *(float4*)(brow + 4) = o1;
    }
}

// ============================================================================
// Row softmax in-place over beta: one block per (b,h,n) row of M=2048.
// ============================================================================
__global__ void __launch_bounds__(256) softmax_kernel(float* __restrict__ beta)
{
    float4* p = (float4*)(beta + (size_t)blockIdx.x * MM);
    const int t = threadIdx.x;
    float4 v0 = p[t];
    float4 v1 = p[t + 256];

    float mx = fmaxf(fmaxf(fmaxf(v0.x, v0.y), fmaxf(v0.z, v0.w)),
                     fmaxf(fmaxf(v1.x, v1.y), fmaxf(v1.z, v1.w)));
    #pragma unroll
    for (int o = 16; o; o >>= 1) mx = fmaxf(mx, __shfl_xor_sync(0xffffffffu, mx, o));

    __shared__ float red[8];
    if ((t & 31) == 0) red[t >> 5] = mx;
    __syncthreads();
    const float bmx = fmaxf(fmaxf(fmaxf(red[0], red[1]), fmaxf(red[2], red[3])),
                            fmaxf(fmaxf(red[4], red[5]), fmaxf(red[6], red[7])));
    __syncthreads();

    v0.x = __expf(v0.x - bmx); v0.y = __expf(v0.y - bmx);
    v0.z = __expf(v0.z - bmx); v0.w = __expf(v0.w - bmx);
    v1.x = __expf(v1.x - bmx); v1.y = __expf(v1.y - bmx);
    v1.z = __expf(v1.z - bmx); v1.w = __expf(v1.w - bmx);

    float s = v0.x + v0.y + v0.z + v0.w + v1.x + v1.y + v1.z + v1.w;
    #pragma unroll
    for (int o = 16; o; o >>= 1) s += __shfl_xor_sync(0xffffffffu, s, o);
    if ((t & 31) == 0) red[t >> 5] = s;
    __syncthreads();
    const float bs = red[0]+red[1]+red[2]+red[3]+red[4]+red[5]+red[6]+red[7];
    const float inv = 1.0f / bs;

    v0.x *= inv; v0.y *= inv; v0.z *= inv; v0.w *= inv;
    v1.x *= inv; v1.y *= inv; v1.z *= inv; v1.w *= inv;
    p[t]       = v0;
    p[t + 256] = v1;
}

// ============================================================================
// wt_V = beta (N x M) @ V (M x 64) per (b,h). 128x64 tile, BK=32.
// Output layout (b,n,h,dk).
// ============================================================================
__global__ void __launch_bounds__(256) av_kernel(const float* __restrict__ beta)
{
    __shared__ float Bs[32][132];
    __shared__ float Vs[32][68];

    const int tid = threadIdx.x;
    const int z   = blockIdx.z;
    const int b   = z >> 4;
    const int h   = z & 15;
    const int n0  = blockIdx.y * 128;

    const float* Bbase = beta + ((size_t)z * NN + n0) * MM;
    const float* Vbase = g_V + (size_t)z * MM * DKK;

    const int trow = (tid >> 4) << 3;   // 8 rows
    const int tcol = (tid & 15) << 2;   // 4 cols

    const int br = tid >> 3;            // 0..31 (row base, +it*32)
    const int bc = (tid & 7) << 2;      // 0..28 step 4 (k within 32)
    const int vr = tid >> 4;            // 0..15 (+it*16)
    const int vc = (tid & 15) << 2;

    float acc[8][4];
    #pragma unroll
    for (int i = 0; i < 8; i++)
        #pragma unroll
        for (int j = 0; j < 4; j++) acc[i][j] = 0.f;

    for (int k0 = 0; k0 < MM; k0 += 32) {
        float4 bv[4], vv[2];
        #pragma unroll
        for (int it = 0; it < 4; it++)
            bv[it] = *(const float4*)(Bbase + (size_t)(br + it*32)*MM + k0 + bc);
        #pragma unroll
        for (int it = 0; it < 2; it++)
            vv[it] = *(const float4*)(Vbase + (size_t)(k0 + vr + it*16)*DKK + vc);
        __syncthreads();
        #pragma unroll
        for (int it = 0; it < 4; it++) {
            const int row = br + it*32;
            Bs[bc+0][row] = bv[it].x; Bs[bc+1][row] = bv[it].y;
            Bs[bc+2][row] = bv[it].z; Bs[bc+3][row] = bv[it].w;
        }
        #pragma unroll
        for (int it = 0; it < 2; it++)
            *(float4*)&Vs[vr + it*16][vc] = vv[it];
        __syncthreads();
        #pragma unroll 8
        for (int k = 0; k < 32; k++) {
            float4 a0 = *(const float4*)&Bs[k][trow];
            float4 a1 = *(const float4*)&Bs[k][trow+4];
            float4 b4 = *(const float4*)&Vs[k][tcol];
            float a[8] = {a0.x,a0.y,a0.z,a0.w,a1.x,a1.y,a1.z,a1.w};
            float bb[4] = {b4.x,b4.y,b4.z,b4.w};
            #pragma unroll
            for (int i = 0; i < 8; i++)
                #pragma unroll
                for (int j = 0; j < 4; j++)
                    acc[i][j] = fmaf(a[i], bb[j], acc[i][j]);
        }
    }

    #pragma unroll
    for (int i = 0; i < 8; i++) {
        const int n = n0 + trow + i;
        float* o = g_Wt + (((size_t)(b*NN + n)*HH + h) << 6) + tcol;
        *(float4*)o = make_float4(acc[i][0], acc[i][1], acc[i][2], acc[i][3]);
    }
}

// ============================================================================
extern "C" void kernel_launch(void* const* d_in, const int* in_sizes, int n_in,
                              void* d_out, int out_size)
{
    const float* X    = (const float*)d_in[0];
    const float* Y    = (const float*)d_in[1];
    const int*   mask = (const int*)  d_in[2];
    const float* Wq   = (const float*)d_in[3];
    const float* bq   = (const float*)d_in[4];
    const float* Wk   = (const float*)d_in[5];
    const float* bk   = (const float*)d_in[6];
    const float* Wv   = (const float*)d_in[7];
    const float* bv   = (const float*)d_in[8];
    const float* Wo   = (const float*)d_in[9];
    const float* bo   = (const float*)d_in[10];
    float* out = (float*)d_out;

    const size_t ATTN = (size_t)BB * NN * DD;           // 8,388,608
    const size_t BETA = (size_t)BB * HH * NN * MM;      // 268,435,456

    void *qp_, *kp_, *vp_, *wp_, *bsp_;
    cudaGetSymbolAddress(&qp_, g_Q);
    cudaGetSymbolAddress(&kp_, g_K);
    cudaGetSymbolAddress(&vp_, g_V);
    cudaGetSymbolAddress(&wp_, g_Wt);
    cudaGetSymbolAddress(&bsp_, g_beta_scratch);

    float* beta = ((size_t)out_size >= ATTN + BETA) ? (out + ATTN)
                                                    : (float*)bsp_;

    const dim3 pgrid(DD/128, RR/128);   // (8, 64)
    proj_kernel<1><<<pgrid, 256>>>(X, Wq, bq, (float*)qp_);
    proj_kernel<1><<<pgrid, 256>>>(Y, Wk, bk, (float*)kp_);
    proj_kernel<1><<<pgrid, 256>>>(Y, Wv, bv, (float*)vp_);

    const int score_smem = 2 * 64 * 132 * (int)sizeof(float);   // 67584
    cudaFuncSetAttribute(scores_kernel,
                         cudaFuncAttributeMaxDynamicSharedMemorySize, score_smem);
    scores_kernel<<<dim3(MM/128, NN/128, BB*HH), 256, score_smem>>>(mask, beta);

    softmax_kernel<<<BB*HH*NN, 256>>>(beta);

    av_kernel<<<dim3(1, NN/128, BB*HH), 256>>>(beta);

    proj_kernel<0><<<pgrid, 256>>>((const float*)wp_, Wo, bo, out);
}

// round 3
// speedup vs baseline: 2.1051x; 2.1051x over previous
#include <cuda_runtime.h>
#include <cuda_bf16.h>
#include <stdint.h>

#define BB 4
#define NN 2048
#define MM 2048
#define DD 1024
#define HH 16
#define DKK 64
#define RR (BB*NN)
#define NEGV -1e32f

#define EL_X ((size_t)RR*DD)     // 8,388,608
#define EL_W ((size_t)DD*DD)     // 1,048,576

// bf16 arena: 12 X-sized slots + 8 weight slots
// slots: 0 XH,1 XL,2 YH,3 YL,4 QH,5 QL,6 KH,7 KL,8 VH,9 VL,10 TH,11 TL
__device__ __nv_bfloat16 g_bf[12*EL_X + 8*EL_W];
__device__ float g_beta_scratch[(size_t)BB*HH*NN*MM];

// ---------------------------------------------------------------------------
__device__ __forceinline__ uint32_t smem_u32(const void* p) {
    uint32_t a;
    asm("{ .reg .u64 t; cvta.to.shared.u64 t, %1; cvt.u32.u64 %0, t; }"
        : "=r"(a) : "l"(p));
    return a;
}

#define CP16(s, g) \
    asm volatile("cp.async.cg.shared.global [%0], [%1], 16;" :: "r"(s), "l"(g))
#define CPC() asm volatile("cp.async.commit_group;" ::: "memory")
#define CPW(n) asm volatile("cp.async.wait_group %0;" :: "n"(n) : "memory")

#define LDSM4(r, addr) \
    asm volatile("ldmatrix.sync.aligned.m8n8.x4.shared.b16 {%0,%1,%2,%3}, [%4];" \
        : "=r"((r)[0]), "=r"((r)[1]), "=r"((r)[2]), "=r"((r)[3]) : "r"(addr))
#define LDSM4T(r, addr) \
    asm volatile("ldmatrix.sync.aligned.m8n8.x4.trans.shared.b16 {%0,%1,%2,%3}, [%4];" \
        : "=r"((r)[0]), "=r"((r)[1]), "=r"((r)[2]), "=r"((r)[3]) : "r"(addr))

#define MMA_BF16(d, a, b0, b1) \
    asm volatile("mma.sync.aligned.m16n8k16.row.col.f32.bf16.bf16.f32 " \
        "{%0,%1,%2,%3}, {%4,%5,%6,%7}, {%8,%9}, {%0,%1,%2,%3};" \
        : "+f"((d)[0]), "+f"((d)[1]), "+f"((d)[2]), "+f"((d)[3]) \
        : "r"((a)[0]), "r"((a)[1]), "r"((a)[2]), "r"((a)[3]), "r"(b0), "r"(b1))

__device__ __forceinline__ uint32_t pack_hi(float x, float y) {
    __nv_bfloat162 v(__float2bfloat16(x), __float2bfloat16(y));
    return *(uint32_t*)&v;
}
__device__ __forceinline__ uint32_t pack_lo(float x, float y) {
    float hx = __bfloat162float(__float2bfloat16(x));
    float hy = __bfloat162float(__float2bfloat16(y));
    __nv_bfloat162 v(__float2bfloat16(x - hx), __float2bfloat16(y - hy));
    return *(uint32_t*)&v;
}

// ---------------------------------------------------------------------------
// fp32 -> bf16 hi/lo split
// ---------------------------------------------------------------------------
__global__ void __launch_bounds__(256) conv_split(const float* __restrict__ src,
                                                  __nv_bfloat16* __restrict__ hi,
                                                  __nv_bfloat16* __restrict__ lo,
                                                  int n4)
{
    int i = blockIdx.x * blockDim.x + threadIdx.x;
    if (i >= n4) return;
    float4 v = ((const float4*)src)[i];
    uint32_t* hp = (uint32_t*)hi;
    uint32_t* lp = (uint32_t*)lo;
    hp[2*i]   = pack_hi(v.x, v.y);
    hp[2*i+1] = pack_hi(v.z, v.w);
    lp[2*i]   = pack_lo(v.x, v.y);
    lp[2*i+1] = pack_lo(v.z, v.w);
}

// ---------------------------------------------------------------------------
// Projection GEMM: C[r,c] = sum_k A[r,k]*W[c,k] + bias[c], split-bf16 3-term.
// 128x128 CTA tile, BK=64, 48 k-tiles (3 phases x 16), cp.async double buffer.
// OUTMODE 0: fp32 row-major out. OUTMODE 1: bf16 hi/lo head-split (b,h,seq,dk).
// smem: As[2] @ 0/9216, Ws[2] @ 18432/27648 (bf16 elems, stride 72). 73728 B.
// ---------------------------------------------------------------------------
template<int OUTMODE>
__global__ void __launch_bounds__(256,2) gemm_proj(
    const __nv_bfloat16* __restrict__ Ah, const __nv_bfloat16* __restrict__ Al,
    const __nv_bfloat16* __restrict__ Wh, const __nv_bfloat16* __restrict__ Wl,
    const float* __restrict__ bias,
    float* __restrict__ outF,
    __nv_bfloat16* __restrict__ outH, __nv_bfloat16* __restrict__ outL)
{
    extern __shared__ __nv_bfloat16 sm[];
    const int tid  = threadIdx.x;
    const int lane = tid & 31;
    const int wid  = tid >> 5;
    const int wm   = wid & 3;      // 4 warp rows x 32
    const int wn   = wid >> 2;     // 2 warp cols x 64
    const int row0 = blockIdx.y * 128;
    const int col0 = blockIdx.x * 128;
    const uint32_t sbase = smem_u32(sm);

    float acc[2][8][4];
    #pragma unroll
    for (int i = 0; i < 2; i++)
        #pragma unroll
        for (int j = 0; j < 8; j++)
            #pragma unroll
            for (int q = 0; q < 4; q++) acc[i][j][q] = 0.f;

    // --- issue tile t (t in [0,48)) into buffer t&1
    #define ISSUE(t) do {                                                      \
        const int p  = (t) >> 4;                                               \
        const int k0 = ((t) & 15) << 6;                                        \
        const __nv_bfloat16* Ap = (p == 1) ? Al : Ah;                          \
        const __nv_bfloat16* Wp = (p == 2) ? Wl : Wh;                          \
        const uint32_t sA = sbase + ((t & 1) * 9216) * 2;                      \
        const uint32_t sW = sbase + (18432 + (t & 1) * 9216) * 2;              \
        _Pragma("unroll")                                                      \
        for (int i_ = 0; i_ < 4; i_++) {                                       \
            int idx = tid + i_ * 256;                                          \
            int r = idx >> 3, ch = idx & 7;                                    \
            CP16(sA + (r * 72 + ch * 8) * 2,                                   \
                 Ap + (size_t)(row0 + r) * DD + k0 + ch * 8);                  \
            CP16(sW + (r * 72 + ch * 8) * 2,                                   \
                 Wp + (size_t)(col0 + r) * DD + k0 + ch * 8);                  \
        }                                                                      \
        CPC();                                                                 \
    } while (0)

    ISSUE(0);
    for (int t = 0; t < 48; t++) {
        if (t + 1 < 48) { ISSUE(t + 1); CPW(1); }
        else            { CPW(0); }
        __syncthreads();
        const uint32_t sA = sbase + ((t & 1) * 9216) * 2;
        const uint32_t sW = sbase + (18432 + (t & 1) * 9216) * 2;
        #pragma unroll
        for (int ks = 0; ks < 4; ks++) {
            uint32_t a[2][4], bq[4][4];
            #pragma unroll
            for (int i = 0; i < 2; i++)
                LDSM4(a[i], sA + ((wm*32 + i*16 + (lane & 15)) * 72
                                  + ks*16 + (lane >> 4) * 8) * 2);
            #pragma unroll
            for (int jj = 0; jj < 4; jj++)
                LDSM4(bq[jj], sW + ((wn*64 + jj*16 + (lane & 15)) * 72
                                    + ks*16 + (lane >> 4) * 8) * 2);
            #pragma unroll
            for (int i = 0; i < 2; i++)
                #pragma unroll
                for (int j = 0; j < 8; j++) {
                    const int jj = j >> 1;
                    uint32_t b0 = (j & 1) ? bq[jj][1] : bq[jj][0];
                    uint32_t b1 = (j & 1) ? bq[jj][3] : bq[jj][2];
                    MMA_BF16(acc[i][j], a[i], b0, b1);
                }
        }
        __syncthreads();
    }
    #undef ISSUE

    // --- epilogue
    const int bb = row0 >> 11;               // whole tile in one batch
    #pragma unroll
    for (int i = 0; i < 2; i++) {
        const int r  = row0 + wm*32 + i*16 + (lane >> 2);
        const int n  = r & 2047;
        #pragma unroll
        for (int j = 0; j < 8; j++) {
            const int c = col0 + wn*64 + j*8 + (lane & 3)*2;
            const float b0v = __ldg(bias + c), b1v = __ldg(bias + c + 1);
            const float v00 = acc[i][j][0] + b0v, v01 = acc[i][j][1] + b1v;
            const float v10 = acc[i][j][2] + b0v, v11 = acc[i][j][3] + b1v;
            if (OUTMODE == 0) {
                *(float2*)(outF + (size_t)r * DD + c)       = make_float2(v00, v01);
                *(float2*)(outF + (size_t)(r + 8) * DD + c) = make_float2(v10, v11);
            } else {
                const int h = c >> 6, dk = c & 63;
                const size_t a0 = ((((size_t)bb*HH + h)*NN + n)      << 6) + dk;
                const size_t a1 = ((((size_t)bb*HH + h)*NN + (n+8))  << 6) + dk;
                *(uint32_t*)(outH + a0) = pack_hi(v00, v01);
                *(uint32_t*)(outL + a0) = pack_lo(v00, v01);
                *(uint32_t*)(outH + a1) = pack_hi(v10, v11);
                *(uint32_t*)(outL + a1) = pack_lo(v10, v11);
            }
        }
    }
}

// ---------------------------------------------------------------------------
// Scores: per (b,h) S = Q @ K^T * 0.125, masked -> beta (raw logits).
// 128x128 tile, d_k=64 fully resident, 3 split phases.
// smem: Qh@0, Ql@9216, Kh@18432, Kl@27648 (stride 72). 73728 B.
// ---------------------------------------------------------------------------
__global__ void __launch_bounds__(256,2) scores_mma(
    const int* __restrict__ mask, float* __restrict__ beta,
    const __nv_bfloat16* __restrict__ QH, const __nv_bfloat16* __restrict__ QL,
    const __nv_bfloat16* __restrict__ KH, const __nv_bfloat16* __restrict__ KL)
{
    extern __shared__ __nv_bfloat16 sm[];
    const int tid  = threadIdx.x;
    const int lane = tid & 31;
    const int wid  = tid >> 5;
    const int wm   = wid & 3;
    const int wn   = wid >> 2;
    const int z    = blockIdx.z;
    const int b    = z >> 4;
    const int m0   = blockIdx.x * 128;
    const int n0   = blockIdx.y * 128;
    const uint32_t sbase = smem_u32(sm);

    const __nv_bfloat16* srcs[4] = {
        QH + ((size_t)z*NN + n0) * DKK, QL + ((size_t)z*NN + n0) * DKK,
        KH + ((size_t)z*MM + m0) * DKK, KL + ((size_t)z*MM + m0) * DKK };

    #pragma unroll
    for (int ts = 0; ts < 4; ts++) {
        #pragma unroll
        for (int i = 0; i < 4; i++) {
            int idx = tid + i * 256;
            int r = idx >> 3, ch = idx & 7;
            CP16(sbase + (ts*9216 + r*72 + ch*8) * 2,
                 srcs[ts] + (size_t)r * DKK + ch * 8);
        }
    }
    CPC(); CPW(0);
    __syncthreads();

    float acc[2][8][4];
    #pragma unroll
    for (int i = 0; i < 2; i++)
        #pragma unroll
        for (int j = 0; j < 8; j++)
            #pragma unroll
            for (int q = 0; q < 4; q++) acc[i][j][q] = 0.f;

    #pragma unroll
    for (int p = 0; p < 3; p++) {
        const uint32_t sA = sbase + ((p == 1) ? 9216 : 0) * 2;
        const uint32_t sB = sbase + ((p == 2) ? 27648 : 18432) * 2;
        #pragma unroll
        for (int ks = 0; ks < 4; ks++) {
            uint32_t a[2][4], bq[4][4];
            #pragma unroll
            for (int i = 0; i < 2; i++)
                LDSM4(a[i], sA + ((wm*32 + i*16 + (lane & 15)) * 72
                                  + ks*16 + (lane >> 4) * 8) * 2);
            #pragma unroll
            for (int jj = 0; jj < 4; jj++)
                LDSM4(bq[jj], sB + ((wn*64 + jj*16 + (lane & 15)) * 72
                                    + ks*16 + (lane >> 4) * 8) * 2);
            #pragma unroll
            for (int i = 0; i < 2; i++)
                #pragma unroll
                for (int j = 0; j < 8; j++) {
                    const int jj = j >> 1;
                    uint32_t b0 = (j & 1) ? bq[jj][1] : bq[jj][0];
                    uint32_t b1 = (j & 1) ? bq[jj][3] : bq[jj][2];
                    MMA_BF16(acc[i][j], a[i], b0, b1);
                }
        }
    }

    const float scl = 0.125f;
    #pragma unroll
    for (int i = 0; i < 2; i++) {
        const int n = n0 + wm*32 + i*16 + (lane >> 2);
        const int* mr0 = mask + ((size_t)b*NN + n) * MM;
        const int* mr1 = mask + ((size_t)b*NN + n + 8) * MM;
        float* br0 = beta + ((size_t)z*NN + n) * MM;
        float* br1 = beta + ((size_t)z*NN + n + 8) * MM;
        #pragma unroll
        for (int j = 0; j < 8; j++) {
            const int c = m0 + wn*64 + j*8 + (lane & 3)*2;
            int2 k0 = *(const int2*)(mr0 + c);
            int2 k1 = *(const int2*)(mr1 + c);
            float2 o0, o1;
            o0.x = (k0.x == 1) ? NEGV : acc[i][j][0] * scl;
            o0.y = (k0.y == 1) ? NEGV : acc[i][j][1] * scl;
            o1.x = (k1.x == 1) ? NEGV : acc[i][j][2] * scl;
            o1.y = (k1.y == 1) ? NEGV : acc[i][j][3] * scl;
            *(float2*)(br0 + c) = o0;
            *(float2*)(br1 + c) = o1;
        }
    }
}

// ---------------------------------------------------------------------------
// Row softmax in-place over beta (unchanged, passing).
// ---------------------------------------------------------------------------
__global__ void __launch_bounds__(256) softmax_kernel(float* __restrict__ beta)
{
    float4* p = (float4*)(beta + (size_t)blockIdx.x * MM);
    const int t = threadIdx.x;
    float4 v0 = p[t];
    float4 v1 = p[t + 256];

    float mx = fmaxf(fmaxf(fmaxf(v0.x, v0.y), fmaxf(v0.z, v0.w)),
                     fmaxf(fmaxf(v1.x, v1.y), fmaxf(v1.z, v1.w)));
    #pragma unroll
    for (int o = 16; o; o >>= 1) mx = fmaxf(mx, __shfl_xor_sync(0xffffffffu, mx, o));

    __shared__ float red[8];
    if ((t & 31) == 0) red[t >> 5] = mx;
    __syncthreads();
    const float bmx = fmaxf(fmaxf(fmaxf(red[0], red[1]), fmaxf(red[2], red[3])),
                            fmaxf(fmaxf(red[4], red[5]), fmaxf(red[6], red[7])));
    __syncthreads();

    v0.x = __expf(v0.x - bmx); v0.y = __expf(v0.y - bmx);
    v0.z = __expf(v0.z - bmx); v0.w = __expf(v0.w - bmx);
    v1.x = __expf(v1.x - bmx); v1.y = __expf(v1.y - bmx);
    v1.z = __expf(v1.z - bmx); v1.w = __expf(v1.w - bmx);

    float s = v0.x + v0.y + v0.z + v0.w + v1.x + v1.y + v1.z + v1.w;
    #pragma unroll
    for (int o = 16; o; o >>= 1) s += __shfl_xor_sync(0xffffffffu, s, o);
    if ((t & 31) == 0) red[t >> 5] = s;
    __syncthreads();
    const float bs = red[0]+red[1]+red[2]+red[3]+red[4]+red[5]+red[6]+red[7];
    const float inv = 1.0f / bs;

    v0.x *= inv; v0.y *= inv; v0.z *= inv; v0.w *= inv;
    v1.x *= inv; v1.y *= inv; v1.z *= inv; v1.w *= inv;
    p[t]       = v0;
    p[t + 256] = v1;
}

// ---------------------------------------------------------------------------
// wt = beta @ V per (b,h). 128(n) x 64(dk) per CTA, K=M=2048, BK=64.
// beta fp32 -> in-kernel hi/lo; V bf16 hi/lo, k-dim via ldmatrix.trans.
// smem: Bh@0 (128*72), Bl@9216, Vh@18432 (64*72), Vl@23040. 55296 B.
// Output: wt hi/lo bf16 in (b,n,h,dk).
// ---------------------------------------------------------------------------
__global__ void __launch_bounds__(256,2) av_mma(
    const float* __restrict__ beta,
    const __nv_bfloat16* __restrict__ VH, const __nv_bfloat16* __restrict__ VL,
    __nv_bfloat16* __restrict__ WtH, __nv_bfloat16* __restrict__ WtL)
{
    extern __shared__ __nv_bfloat16 sm[];
    const int tid  = threadIdx.x;
    const int lane = tid & 31;
    const int wid  = tid >> 5;       // warp_m: 8 warps x 16 rows
    const int z    = blockIdx.y;
    const int b    = z >> 4;
    const int h    = z & 15;
    const int n0   = blockIdx.x * 128;
    const uint32_t sbase = smem_u32(sm);

    const float* Bsrc = beta + ((size_t)z*NN + n0) * MM;
    const __nv_bfloat16* Vh_g = VH + (size_t)z * MM * DKK;
    const __nv_bfloat16* Vl_g = VL + (size_t)z * MM * DKK;

    float acc[8][4];
    #pragma unroll
    for (int j = 0; j < 8; j++)
        #pragma unroll
        for (int q = 0; q < 4; q++) acc[j][q] = 0.f;

    for (int k0 = 0; k0 < MM; k0 += 64) {
        // beta tile 128x64 fp32 -> Bh/Bl bf16
        #pragma unroll
        for (int i = 0; i < 8; i++) {
            int idx = tid + i * 256;
            int r = idx >> 4, ch = idx & 15;
            float4 v = *(const float4*)(Bsrc + (size_t)r * MM + k0 + ch * 4);
            uint32_t* ph = (uint32_t*)(sm + r*72 + ch*4);
            uint32_t* pl = (uint32_t*)(sm + 9216 + r*72 + ch*4);
            ph[0] = pack_hi(v.x, v.y); ph[1] = pack_hi(v.z, v.w);
            pl[0] = pack_lo(v.x, v.y); pl[1] = pack_lo(v.z, v.w);
        }
        // V tiles 64x64 bf16 hi/lo
        #pragma unroll
        for (int i = 0; i < 4; i++) {
            int idx = tid + i * 256;
            int ts = idx >> 9, r = (idx >> 3) & 63, ch = idx & 7;
            const __nv_bfloat16* vs = ts ? Vl_g : Vh_g;
            *(uint4*)(sm + 18432 + ts*4608 + r*72 + ch*8) =
                *(const uint4*)(vs + (size_t)(k0 + r) * DKK + ch * 8);
        }
        __syncthreads();

        #pragma unroll
        for (int p = 0; p < 3; p++) {
            const uint32_t sA = sbase + ((p == 1) ? 9216 : 0) * 2;
            const uint32_t sV = sbase + (18432 + ((p == 2) ? 4608 : 0)) * 2;
            #pragma unroll
            for (int ks = 0; ks < 4; ks++) {
                uint32_t a[4], bq[4][4];
                LDSM4(a, sA + ((wid*16 + (lane & 15)) * 72
                               + ks*16 + (lane >> 4) * 8) * 2);
                #pragma unroll
                for (int jj = 0; jj < 4; jj++)
                    LDSM4T(bq[jj], sV + ((ks*16 + ((lane >> 3) & 1)*8 + (lane & 7)) * 72
                                         + jj*16 + (lane >> 4) * 8) * 2);
                #pragma unroll
                for (int j = 0; j < 8; j++) {
                    const int jj = j >> 1;
                    uint32_t b0 = (j & 1) ? bq[jj][2] : bq[jj][0];
                    uint32_t b1 = (j & 1) ? bq[jj][3] : bq[jj][1];
                    MMA_BF16(acc[j], a, b0, b1);
                }
            }
        }
        __syncthreads();
    }

    // epilogue: wt (b,n,h,dk) bf16 hi/lo
    const int n = n0 + wid*16 + (lane >> 2);
    #pragma unroll
    for (int j = 0; j < 8; j++) {
        const int dk = j*8 + (lane & 3)*2;
        const size_t a0 = ((((size_t)b*NN + n)    * HH + h) << 6) + dk;
        const size_t a1 = ((((size_t)b*NN + n + 8)* HH + h) << 6) + dk;
        *(uint32_t*)(WtH + a0) = pack_hi(acc[j][0], acc[j][1]);
        *(uint32_t*)(WtL + a0) = pack_lo(acc[j][0], acc[j][1]);
        *(uint32_t*)(WtH + a1) = pack_hi(acc[j][2], acc[j][3]);
        *(uint32_t*)(WtL + a1) = pack_lo(acc[j][2], acc[j][3]);
    }
}

// ============================================================================
extern "C" void kernel_launch(void* const* d_in, const int* in_sizes, int n_in,
                              void* d_out, int out_size)
{
    const float* X    = (const float*)d_in[0];
    const float* Y    = (const float*)d_in[1];
    const int*   mask = (const int*)  d_in[2];
    const float* Wq   = (const float*)d_in[3];
    const float* bq   = (const float*)d_in[4];
    const float* Wk   = (const float*)d_in[5];
    const float* bk   = (const float*)d_in[6];
    const float* Wv   = (const float*)d_in[7];
    const float* bv   = (const float*)d_in[8];
    const float* Wo   = (const float*)d_in[9];
    const float* bo   = (const float*)d_in[10];
    float* out = (float*)d_out;

    const size_t ATTN = (size_t)BB * NN * DD;
    const size_t BETA = (size_t)BB * HH * NN * MM;

    void *bfp_, *bsp_;
    cudaGetSymbolAddress(&bfp_, g_bf);
    cudaGetSymbolAddress(&bsp_, g_beta_scratch);
    __nv_bfloat16* bf = (__nv_bfloat16*)bfp_;

    __nv_bfloat16* XH = bf + 0*EL_X;  __nv_bfloat16* XL = bf + 1*EL_X;
    __nv_bfloat16* YH = bf + 2*EL_X;  __nv_bfloat16* YL = bf + 3*EL_X;
    __nv_bfloat16* QH = bf + 4*EL_X;  __nv_bfloat16* QL = bf + 5*EL_X;
    __nv_bfloat16* KH = bf + 6*EL_X;  __nv_bfloat16* KL = bf + 7*EL_X;
    __nv_bfloat16* VH = bf + 8*EL_X;  __nv_bfloat16* VL = bf + 9*EL_X;
    __nv_bfloat16* TH = bf + 10*EL_X; __nv_bfloat16* TL = bf + 11*EL_X;
    __nv_bfloat16* W0 = bf + 12*EL_X;
    __nv_bfloat16* WqH = W0 + 0*EL_W; __nv_bfloat16* WqL = W0 + 1*EL_W;
    __nv_bfloat16* WkH = W0 + 2*EL_W; __nv_bfloat16* WkL = W0 + 3*EL_W;
    __nv_bfloat16* WvH = W0 + 4*EL_W; __nv_bfloat16* WvL = W0 + 5*EL_W;
    __nv_bfloat16* WoH = W0 + 6*EL_W; __nv_bfloat16* WoL = W0 + 7*EL_W;

    float* beta = ((size_t)out_size >= ATTN + BETA) ? (out + ATTN)
                                                    : (float*)bsp_;

    const int SMP = 73728;   // gemm_proj / scores
    const int SMA = 55296;   // av
    cudaFuncSetAttribute(gemm_proj<0>, cudaFuncAttributeMaxDynamicSharedMemorySize, SMP);
    cudaFuncSetAttribute(gemm_proj<1>, cudaFuncAttributeMaxDynamicSharedMemorySize, SMP);
    cudaFuncSetAttribute(scores_mma,   cudaFuncAttributeMaxDynamicSharedMemorySize, SMP);
    cudaFuncSetAttribute(av_mma,       cudaFuncAttributeMaxDynamicSharedMemorySize, SMA);

    const int n4x = (int)(EL_X / 4);
    const int n4w = (int)(EL_W / 4);
    conv_split<<<(n4x + 255)/256, 256>>>(X,  XH, XL, n4x);
    conv_split<<<(n4x + 255)/256, 256>>>(Y,  YH, YL, n4x);
    conv_split<<<(n4w + 255)/256, 256>>>(Wq, WqH, WqL, n4w);
    conv_split<<<(n4w + 255)/256, 256>>>(Wk, WkH, WkL, n4w);
    conv_split<<<(n4w + 255)/256, 256>>>(Wv, WvH, WvL, n4w);
    conv_split<<<(n4w + 255)/256, 256>>>(Wo, WoH, WoL, n4w);

    const dim3 pgrid(DD/128, RR/128);   // (8, 64)
    gemm_proj<1><<<pgrid, 256, SMP>>>(XH, XL, WqH, WqL, bq, nullptr, QH, QL);
    gemm_proj<1><<<pgrid, 256, SMP>>>(YH, YL, WkH, WkL, bk, nullptr, KH, KL);
    gemm_proj<1><<<pgrid, 256, SMP>>>(YH, YL, WvH, WvL, bv, nullptr, VH, VL);

    scores_mma<<<dim3(MM/128, NN/128, BB*HH), 256, SMP>>>(mask, beta, QH, QL, KH, KL);

    softmax_kernel<<<BB*HH*NN, 256>>>(beta);

    av_mma<<<dim3(NN/128, BB*HH), 256, SMA>>>(beta, VH, VL, TH, TL);

    gemm_proj<0><<<pgrid, 256, SMP>>>(TH, TL, WoH, WoL, bo, out, nullptr, nullptr);
}